// round 14
// baseline (speedup 1.0000x reference)
#include <cuda_runtime.h>
#include <cuda_fp16.h>
#include <math.h>
#include <stdint.h>

// ---------------- problem constants ----------------
#define NB    1024
#define MT    64
#define DD    512
#define NH    8
#define HD    64
#define DEPTH 4
#define FF    2048
#define NOBJ  8192
#define NTRI  10240
#define BMT   (NB*MT)   // 65536 rows
#define QS    1536      // packed qkv row stride

// ---------------- static scratch ----------------
#define W_TOT 12845056
__device__ __half g_whi[W_TOT];
__device__ float  g_bqkv[DEPTH*QS];
__device__ float  g_x[BMT*DD];
__device__ __half g_ha [BMT*DD];
__device__ __half g_qkv[(size_t)BMT*QS];
__device__ __half g_ata[BMT*DD];
__device__ __half g_ffa[(size_t)BMT*FF];
__device__ __half g_bxa[NOBJ*DD];
__device__ float  g_objbase[NOBJ*DD];
__device__ float  g_objtok [NOBJ*DD];
__device__ unsigned char g_mask[BMT];
__device__ int    g_first[NB];

// weight pool offsets (elements)
#define OFF_BW2 0
#define LYR_STRIDE 3145728
#define OFF_L(l)   (262144 + (l)*LYR_STRIDE)
#define OFF_QKV(l) OFF_L(l)
#define OFF_WO(l)  (OFF_L(l)+786432)
#define OFF_F1(l)  (OFF_L(l)+1048576)
#define OFF_F2(l)  (OFF_L(l)+2097152)

__device__ __forceinline__ float gelu_f(float x) {
    return 0.5f * x * (1.0f + erff(x * 0.70710678118654752440f));
}
__device__ __forceinline__ uint32_t smem_u32(const void* p) {
    uint32_t a;
    asm("{ .reg .u64 t; cvta.to.shared.u64 t, %1; cvt.u32.u64 %0, t; }" : "=r"(a) : "l"(p));
    return a;
}

// ---------------- MMA primitives (family-wide, sm_80+) ----------------
__device__ __forceinline__ void ldm4(uint32_t* r, uint32_t addr) {
    asm volatile("ldmatrix.sync.aligned.m8n8.x4.shared.b16 {%0,%1,%2,%3}, [%4];"
        : "=r"(r[0]), "=r"(r[1]), "=r"(r[2]), "=r"(r[3]) : "r"(addr));
}
__device__ __forceinline__ void mma_f16(float* d, const uint32_t* a, const uint32_t* b) {
    asm volatile("mma.sync.aligned.m16n8k16.row.col.f32.f16.f16.f32 "
        "{%0,%1,%2,%3}, {%4,%5,%6,%7}, {%8,%9}, {%0,%1,%2,%3};"
        : "+f"(d[0]), "+f"(d[1]), "+f"(d[2]), "+f"(d[3])
        : "r"(a[0]), "r"(a[1]), "r"(a[2]), "r"(a[3]), "r"(b[0]), "r"(b[1]));
}
__device__ __forceinline__ void cpasync16(uint32_t sdst, const void* gsrc) {
    asm volatile("cp.async.cg.shared.global [%0], [%1], 16;" :: "r"(sdst), "l"(gsrc));
}
#define CP_COMMIT() asm volatile("cp.async.commit_group;" ::: "memory")
#define CP_WAIT1()  asm volatile("cp.async.wait_group 1;" ::: "memory")

// ---------------- fp16 single-term GEMM, 128x256 tile, BK=64, warp tile 64x64 ----------------
// C[M,N] = A[M,K](fp16) @ B^T[N,K](fp16) + bias (+gelu) (+res | half-out)
// 8 warps (2x4), 1 CTA/SM, 3-stage cp.async pipeline.
#define BM 128
#define BN 256
#define BK 64
#define LDE 72          // padded smem row stride in elements (144 B)
#define A_OFF 0         // 128*144 = 18432
#define B_OFF 18432     // 256*144 = 36864
#define STG_SZ 55296
#define NSTG 3
#define GSM_TOTAL (NSTG*STG_SZ)   // 165888 B

template<bool GELU, bool HALFOUT>
__global__ void __launch_bounds__(256, 1) gemm2(
    const __half* __restrict__ A, const __half* __restrict__ B,
    const float* __restrict__ bias, const float* __restrict__ res,
    float* __restrict__ C, __half* __restrict__ Ch, int K, int ldc)
{
    extern __shared__ char sm[];
    const uint32_t smb = smem_u32(sm);
    const int tid  = threadIdx.x;
    const int lane = tid & 31;
    const int wid  = tid >> 5;
    const int wm   = (wid & 1) * 64;
    const int wn   = (wid >> 1) * 64;
    const int bn   = blockIdx.x * BN;
    const int bm   = blockIdx.y * BM;

    const int aRow = lane & 15;
    const int aK   = (lane >> 4) << 3;
    const int bRow = (lane & 7) + ((lane >> 4) << 3);
    const int bK   = ((lane >> 3) & 1) << 3;

    float d[4][8][4];
#pragma unroll
    for (int i = 0; i < 4; i++)
#pragma unroll
        for (int j = 0; j < 8; j++)
#pragma unroll
            for (int u = 0; u < 4; u++) d[i][j][u] = 0.f;

    const int NKT = K >> 6;     // 64-wide K chunks

    auto load_stage = [&](int kt, int s) {
        const uint32_t stg = smb + (uint32_t)s * STG_SZ;
        const int k0 = kt << 6;
        // A: 128 rows x 128B = 1024 16B-chunks (4/thread)
#pragma unroll
        for (int i = 0; i < 4; i++) {
            int id = tid + i * 256;
            int r = id >> 3, c = id & 7;
            uint32_t so = (uint32_t)(r * 144 + c * 16);
            cpasync16(stg + A_OFF + so, A + (size_t)(bm + r) * K + k0 + c * 8);
        }
        // B: 256 rows x 128B = 2048 16B-chunks (8/thread)
#pragma unroll
        for (int i = 0; i < 8; i++) {
            int id = tid + i * 256;
            int r = id >> 3, c = id & 7;
            uint32_t so = (uint32_t)(r * 144 + c * 16);
            cpasync16(stg + B_OFF + so, B + (size_t)(bn + r) * K + k0 + c * 8);
        }
    };

    auto compute = [&](int s) {
        const uint32_t stg = smb + (uint32_t)s * STG_SZ;
#pragma unroll
        for (int ks = 0; ks < 4; ks++) {
            const int kofs = ks * 16;
            uint32_t ah[4][4], bh[4][4];
#pragma unroll
            for (int mf = 0; mf < 4; mf++) {
                uint32_t ao = (uint32_t)((wm + mf*16 + aRow) * LDE + kofs + aK) * 2;
                ldm4(ah[mf], stg + A_OFF + ao);
            }
#pragma unroll
            for (int g = 0; g < 4; g++) {
                uint32_t bo = (uint32_t)((wn + g*16 + bRow) * LDE + kofs + bK) * 2;
                ldm4(bh[g], stg + B_OFF + bo);
            }
#pragma unroll
            for (int mf = 0; mf < 4; mf++)
#pragma unroll
                for (int nf = 0; nf < 8; nf++)
                    mma_f16(d[mf][nf], ah[mf], &bh[nf >> 1][(nf & 1) * 2]);
        }
    };

    load_stage(0, 0); CP_COMMIT();
    load_stage(1, 1); CP_COMMIT();
    for (int kt = 0; kt < NKT; kt++) {
        const int s = kt % 3;
        CP_WAIT1();
        __syncthreads();
        if (kt + 2 < NKT)
            load_stage(kt + 2, (kt + 2) % 3);
        CP_COMMIT();
        compute(s);
    }

    // ---- epilogue ----
#pragma unroll
    for (int mf = 0; mf < 4; mf++) {
        const int r0 = bm + wm + mf * 16 + (lane >> 2);
#pragma unroll
        for (int nf = 0; nf < 8; nf++) {
            const int c = bn + wn + nf * 8 + (lane & 3) * 2;
            float2 bv = *(const float2*)(bias + c);
            float v00 = d[mf][nf][0] + bv.x, v01 = d[mf][nf][1] + bv.y;
            float v10 = d[mf][nf][2] + bv.x, v11 = d[mf][nf][3] + bv.y;
            if (GELU) {
                v00 = gelu_f(v00); v01 = gelu_f(v01);
                v10 = gelu_f(v10); v11 = gelu_f(v11);
            }
            const size_t o0 = (size_t)r0 * ldc + c;
            const size_t o1 = (size_t)(r0 + 8) * ldc + c;
            if (HALFOUT) {
                *(half2*)(Ch + o0) = __floats2half2_rn(v00, v01);
                *(half2*)(Ch + o1) = __floats2half2_rn(v10, v11);
            } else {
                float2 w0 = make_float2(v00, v01);
                float2 w1 = make_float2(v10, v11);
                if (res) {
                    float2 rr0 = *(const float2*)(res + o0);
                    float2 rr1 = *(const float2*)(res + o1);
                    w0.x += rr0.x; w0.y += rr0.y;
                    w1.x += rr1.x; w1.y += rr1.y;
                }
                *(float2*)(C + o0) = w0;
                *(float2*)(C + o1) = w1;
            }
        }
    }
}

// ---------------- weight transpose + fp16 cast: W[K,N] -> out[N,K] ----------------
__global__ void __launch_bounds__(256) tsplit_k(
    const float* __restrict__ W, __half* __restrict__ oh, int K, int N)
{
    __shared__ float tile[32][33];
    int tx = threadIdx.x & 31, ty = threadIdx.x >> 5;
    int n0 = blockIdx.x * 32, k0 = blockIdx.y * 32;
#pragma unroll
    for (int j = 0; j < 4; j++)
        tile[ty + j * 8][tx] = W[(size_t)(k0 + ty + j * 8) * N + n0 + tx];
    __syncthreads();
#pragma unroll
    for (int j = 0; j < 4; j++) {
        int n = n0 + ty + j * 8;
        int k = k0 + tx;
        oh[(size_t)n * K + k] = __float2half_rn(tile[tx][ty + j * 8]);
    }
}

// ---------------- pack q/k/v biases ----------------
__global__ void packb_k(const float* __restrict__ bq, const float* __restrict__ bk,
                        const float* __restrict__ bv, float* __restrict__ out)
{
    int i = blockIdx.x * blockDim.x + threadIdx.x;
    if (i >= DEPTH * QS) return;
    int l = i / QS, c = i % QS;
    float v;
    if (c < 512)       v = bq[l * 512 + c];
    else if (c < 1024) v = bk[l * 512 + c - 512];
    else               v = bv[l * 512 + c - 1024];
    out[i] = v;
}

// ---------------- LayerNorm -> fp16 ----------------
__global__ void __launch_bounds__(128) ln_k(
    const float* __restrict__ x, const float* __restrict__ g,
    const float* __restrict__ bvec, __half* __restrict__ oa)
{
    int row = blockIdx.x;
    const float* xr = x + (size_t)row * DD;
    int tid = threadIdx.x;
    float4 v = *(const float4*)(xr + tid * 4);
    float s  = v.x + v.y + v.z + v.w;
    float sq = v.x*v.x + v.y*v.y + v.z*v.z + v.w*v.w;
#pragma unroll
    for (int off = 16; off; off >>= 1) {
        s  += __shfl_xor_sync(0xffffffffu, s,  off);
        sq += __shfl_xor_sync(0xffffffffu, sq, off);
    }
    __shared__ float ss[4], ssq[4];
    int w = tid >> 5, l = tid & 31;
    if (l == 0) { ss[w] = s; ssq[w] = sq; }
    __syncthreads();
    s  = ss[0] + ss[1] + ss[2] + ss[3];
    sq = ssq[0] + ssq[1] + ssq[2] + ssq[3];
    float mean = s * (1.f / DD);
    float var  = sq * (1.f / DD) - mean * mean;
    float rstd = rsqrtf(var + 1e-5f);
    float4 gv = *(const float4*)(g    + tid * 4);
    float4 bb = *(const float4*)(bvec + tid * 4);
    float o0 = (v.x - mean) * rstd * gv.x + bb.x;
    float o1 = (v.y - mean) * rstd * gv.y + bb.y;
    float o2 = (v.z - mean) * rstd * gv.z + bb.z;
    float o3 = (v.w - mean) * rstd * gv.w + bb.w;
    size_t ob = (size_t)row * DD + tid * 4;
    *(half2*)(oa + ob)     = __floats2half2_rn(o0, o1);
    *(half2*)(oa + ob + 2) = __floats2half2_rn(o2, o3);
}

// ---------------- box MLP stage 1 -> fp16 ----------------
__global__ void __launch_bounds__(128) box_k(
    const float* __restrict__ boxes, const float* __restrict__ bw1,
    const float* __restrict__ bb1, const float* __restrict__ blg,
    const float* __restrict__ blb, __half* __restrict__ oa)
{
    int r = blockIdx.x;
    float b0 = boxes[r*4+0], b1 = boxes[r*4+1], b2 = boxes[r*4+2], b3 = boxes[r*4+3];
    int tid = threadIdx.x;
    int d0 = tid * 4;
    float4 w0 = *(const float4*)(bw1 + d0);
    float4 w1 = *(const float4*)(bw1 + 512  + d0);
    float4 w2 = *(const float4*)(bw1 + 1024 + d0);
    float4 w3 = *(const float4*)(bw1 + 1536 + d0);
    float4 bbv = *(const float4*)(bb1 + d0);
    float t[4];
    t[0] = bbv.x + b0*w0.x + b1*w1.x + b2*w2.x + b3*w3.x;
    t[1] = bbv.y + b0*w0.y + b1*w1.y + b2*w2.y + b3*w3.y;
    t[2] = bbv.z + b0*w0.z + b1*w1.z + b2*w2.z + b3*w3.z;
    t[3] = bbv.w + b0*w0.w + b1*w1.w + b2*w2.w + b3*w3.w;
    float s  = t[0]+t[1]+t[2]+t[3];
    float sq = t[0]*t[0]+t[1]*t[1]+t[2]*t[2]+t[3]*t[3];
#pragma unroll
    for (int off = 16; off; off >>= 1) {
        s  += __shfl_xor_sync(0xffffffffu, s,  off);
        sq += __shfl_xor_sync(0xffffffffu, sq, off);
    }
    __shared__ float ss[4], ssq[4];
    int w = tid >> 5, l = tid & 31;
    if (l == 0) { ss[w] = s; ssq[w] = sq; }
    __syncthreads();
    s  = ss[0] + ss[1] + ss[2] + ss[3];
    sq = ssq[0] + ssq[1] + ssq[2] + ssq[3];
    float mean = s * (1.f / DD);
    float var  = sq * (1.f / DD) - mean * mean;
    float rstd = rsqrtf(var + 1e-5f);
    float4 gv = *(const float4*)(blg + d0);
    float4 bv = *(const float4*)(blb + d0);
    float o0 = gelu_f((t[0]-mean)*rstd*gv.x + bv.x);
    float o1 = gelu_f((t[1]-mean)*rstd*gv.y + bv.y);
    float o2 = gelu_f((t[2]-mean)*rstd*gv.z + bv.z);
    float o3 = gelu_f((t[3]-mean)*rstd*gv.w + bv.w);
    size_t ob = (size_t)r * DD + d0;
    *(half2*)(oa + ob)     = __floats2half2_rn(o0, o1);
    *(half2*)(oa + ob + 2) = __floats2half2_rn(o2, o3);
}

// ---------------- gather obj embeddings ----------------
__global__ void __launch_bounds__(128) gather_k(
    const int* __restrict__ objs, const float* __restrict__ obj_emb,
    float* __restrict__ out)
{
    int r = blockIdx.x;
    int o = objs[r];
    float4 v = *(const float4*)(obj_emb + (size_t)o * DD + threadIdx.x * 4);
    *(float4*)(out + (size_t)r * DD + threadIdx.x * 4) = v;
}

// ---------------- first[i] ----------------
__global__ void first_k(const int* __restrict__ t2i, int* __restrict__ first)
{
    int i = blockIdx.x * blockDim.x + threadIdx.x;
    if (i >= NB) return;
    int lo = 0, hi = NTRI;
    while (lo < hi) {
        int mid = (lo + hi) >> 1;
        if (t2i[mid] < i) lo = mid + 1; else hi = mid;
    }
    first[i] = lo;
}

// ---------------- scatter ----------------
__global__ void __launch_bounds__(128) scatter_k(
    const int* __restrict__ triples, const int* __restrict__ t2i,
    const int* __restrict__ first, const float* __restrict__ objtok,
    const float* __restrict__ pred_emb, float* __restrict__ x,
    unsigned char* __restrict__ mask)
{
    int t = blockIdx.x;
    int j = blockIdx.y;
    int img = t2i[t];
    int pos = t - first[img];
    int slot = pos * 3 + j;
    if (slot >= MT) return;
    const float* src;
    if (j == 0)      src = objtok   + (size_t)triples[t*3+0] * DD;
    else if (j == 1) src = pred_emb + (size_t)triples[t*3+1] * DD;
    else             src = objtok   + (size_t)triples[t*3+2] * DD;
    float* dst = x + ((size_t)img * MT + slot) * DD;
    int tid = threadIdx.x;
    *(float4*)(dst + tid * 4) = *(const float4*)(src + tid * 4);
    if (tid == 0) mask[img * MT + slot] = 1;
}

// ---------------- attention (packed qkv fp16 in, fp16 out) ----------------
__global__ void __launch_bounds__(256) attn_k(
    const __half* __restrict__ qkv, const unsigned char* __restrict__ mask,
    __half* __restrict__ oa)
{
    __shared__ float sA[64][65];
    __shared__ float sB[64][65];
    int b = blockIdx.x, h = blockIdx.y;
    int tid = threadIdx.x;
    int tx = tid & 15, ty = tid >> 4;
    const size_t qb = ((size_t)b * MT) * QS + (size_t)h * HD;
    const size_t ob = ((size_t)b * MT) * DD + (size_t)h * HD;

#pragma unroll
    for (int i = 0; i < 8; i++) {
        int idx = tid + i * 256;
        int m = idx >> 5, dd = (idx & 31) * 2;
        half2 q2 = *(const half2*)(qkv + qb + (size_t)m * QS + dd);
        half2 k2 = *(const half2*)(qkv + qb + 512 + (size_t)m * QS + dd);
        float2 qf = __half22float2(q2);
        float2 kf = __half22float2(k2);
        sA[m][dd]     = qf.x; sA[m][dd + 1] = qf.y;
        sB[m][dd]     = kf.x; sB[m][dd + 1] = kf.y;
    }
    __syncthreads();

    bool mv[4];
#pragma unroll
    for (int j = 0; j < 4; j++) mv[j] = mask[b * MT + tx * 4 + j] != 0;

    float sc[4][4];
#pragma unroll
    for (int i = 0; i < 4; i++)
#pragma unroll
        for (int j = 0; j < 4; j++) sc[i][j] = 0.f;

    for (int dd = 0; dd < 64; dd++) {
        float a[4], bb[4];
#pragma unroll
        for (int i = 0; i < 4; i++) a[i]  = sA[ty*4+i][dd];
#pragma unroll
        for (int j = 0; j < 4; j++) bb[j] = sB[tx*4+j][dd];
#pragma unroll
        for (int i = 0; i < 4; i++)
#pragma unroll
            for (int j = 0; j < 4; j++)
                sc[i][j] = fmaf(a[i], bb[j], sc[i][j]);
    }
#pragma unroll
    for (int i = 0; i < 4; i++)
#pragma unroll
        for (int j = 0; j < 4; j++)
            sc[i][j] = mv[j] ? sc[i][j] * 0.125f : -1e9f;

#pragma unroll
    for (int i = 0; i < 4; i++) {
        float mx = fmaxf(fmaxf(sc[i][0], sc[i][1]), fmaxf(sc[i][2], sc[i][3]));
#pragma unroll
        for (int off = 8; off; off >>= 1)
            mx = fmaxf(mx, __shfl_xor_sync(0xffffffffu, mx, off));
        float sum = 0.f;
#pragma unroll
        for (int j = 0; j < 4; j++) { sc[i][j] = expf(sc[i][j] - mx); sum += sc[i][j]; }
#pragma unroll
        for (int off = 8; off; off >>= 1)
            sum += __shfl_xor_sync(0xffffffffu, sum, off);
        float inv = 1.0f / sum;
#pragma unroll
        for (int j = 0; j < 4; j++) sc[i][j] *= inv;
    }
    __syncthreads();

#pragma unroll
    for (int i = 0; i < 4; i++)
#pragma unroll
        for (int j = 0; j < 4; j++)
            sB[ty*4+i][tx*4+j] = sc[i][j];
#pragma unroll
    for (int i = 0; i < 8; i++) {
        int idx = tid + i * 256;
        int m = idx >> 5, dd = (idx & 31) * 2;
        half2 v2 = *(const half2*)(qkv + qb + 1024 + (size_t)m * QS + dd);
        float2 vf = __half22float2(v2);
        sA[m][dd]     = vf.x; sA[m][dd + 1] = vf.y;
    }
    __syncthreads();

    float o[4][4];
#pragma unroll
    for (int i = 0; i < 4; i++)
#pragma unroll
        for (int j = 0; j < 4; j++) o[i][j] = 0.f;
    for (int kk = 0; kk < 64; kk++) {
        float p[4], vv[4];
#pragma unroll
        for (int i = 0; i < 4; i++) p[i]  = sB[ty*4+i][kk];
#pragma unroll
        for (int j = 0; j < 4; j++) vv[j] = sA[kk][tx*4+j];
#pragma unroll
        for (int i = 0; i < 4; i++)
#pragma unroll
            for (int j = 0; j < 4; j++)
                o[i][j] = fmaf(p[i], vv[j], o[i][j]);
    }
#pragma unroll
    for (int i = 0; i < 4; i++) {
        size_t ro = ob + (size_t)(ty*4+i) * DD + tx*4;
        *(half2*)(oa + ro)     = __floats2half2_rn(o[i][0], o[i][1]);
        *(half2*)(oa + ro + 2) = __floats2half2_rn(o[i][2], o[i][3]);
    }
}

// ---------------- host launcher ----------------
extern "C" void kernel_launch(void* const* d_in, const int* in_sizes, int n_in,
                              void* d_out, int out_size)
{
    (void)in_sizes; (void)n_in; (void)out_size;
    const int*   objs    = (const int*)  d_in[0];
    const float* boxes   = (const float*)d_in[1];
    const int*   triples = (const int*)  d_in[2];
    const int*   t2i     = (const int*)  d_in[4];
    const float* obj_emb = (const float*)d_in[5];
    const float* pred_emb= (const float*)d_in[6];
    const float* bw1     = (const float*)d_in[7];
    const float* bb1     = (const float*)d_in[8];
    const float* blg     = (const float*)d_in[9];
    const float* blb     = (const float*)d_in[10];
    const float* bw2     = (const float*)d_in[11];
    const float* bb2     = (const float*)d_in[12];
    const float* ln1g    = (const float*)d_in[13];
    const float* ln1b    = (const float*)d_in[14];
    const float* wq      = (const float*)d_in[15];
    const float* bq      = (const float*)d_in[16];
    const float* wk      = (const float*)d_in[17];
    const float* bk      = (const float*)d_in[18];
    const float* wv      = (const float*)d_in[19];
    const float* bv      = (const float*)d_in[20];
    const float* wo      = (const float*)d_in[21];
    const float* bo      = (const float*)d_in[22];
    const float* ln2g    = (const float*)d_in[23];
    const float* ln2b    = (const float*)d_in[24];
    const float* wf1     = (const float*)d_in[25];
    const float* bf1     = (const float*)d_in[26];
    const float* wf2     = (const float*)d_in[27];
    const float* bf2     = (const float*)d_in[28];
    float* outp = (float*)d_out;

    float *x, *objbase, *objtok, *bqkv;
    __half *whi, *ha, *qkv, *ata, *ffa, *bxa;
    unsigned char* mask;
    int* first;
    cudaGetSymbolAddress((void**)&x,       g_x);
    cudaGetSymbolAddress((void**)&qkv,     g_qkv);
    cudaGetSymbolAddress((void**)&objbase, g_objbase);
    cudaGetSymbolAddress((void**)&objtok,  g_objtok);
    cudaGetSymbolAddress((void**)&mask,    g_mask);
    cudaGetSymbolAddress((void**)&first,   g_first);
    cudaGetSymbolAddress((void**)&bqkv,    g_bqkv);
    cudaGetSymbolAddress((void**)&whi,     g_whi);
    cudaGetSymbolAddress((void**)&ha,      g_ha);
    cudaGetSymbolAddress((void**)&ata,     g_ata);
    cudaGetSymbolAddress((void**)&ffa,     g_ffa);
    cudaGetSymbolAddress((void**)&bxa,     g_bxa);

    cudaFuncSetAttribute(gemm2<false,false>, cudaFuncAttributeMaxDynamicSharedMemorySize, GSM_TOTAL);
    cudaFuncSetAttribute(gemm2<false,true>,  cudaFuncAttributeMaxDynamicSharedMemorySize, GSM_TOTAL);
    cudaFuncSetAttribute(gemm2<true,true>,   cudaFuncAttributeMaxDynamicSharedMemorySize, GSM_TOTAL);

    // launch order: #3 (0-based) is the objtok GEMM -> that's what ncu profiles
    tsplit_k<<<dim3(DD/32, DD/32), 256>>>(bw2, whi + OFF_BW2, DD, DD);                  // 0
    box_k<<<NOBJ, 128>>>(boxes, bw1, bb1, blg, blb, bxa);                               // 1
    gather_k<<<NOBJ, 128>>>(objs, obj_emb, objbase);                                    // 2
    gemm2<false,false><<<dim3(DD/BN, NOBJ/BM), 256, GSM_TOTAL>>>(                       // 3
        bxa, whi + OFF_BW2, bb2, objbase, objtok, nullptr, DD, DD);
    first_k<<<(NB + 127)/128, 128>>>(t2i, first);                                       // 4

    // remaining weight prep
    for (int l = 0; l < DEPTH; l++) {
        size_t wofs = (size_t)l * DD * DD;
        tsplit_k<<<dim3(DD/32, DD/32), 256>>>(wq + wofs, whi + OFF_QKV(l),          DD, DD);
        tsplit_k<<<dim3(DD/32, DD/32), 256>>>(wk + wofs, whi + OFF_QKV(l) + 262144, DD, DD);
        tsplit_k<<<dim3(DD/32, DD/32), 256>>>(wv + wofs, whi + OFF_QKV(l) + 524288, DD, DD);
        tsplit_k<<<dim3(DD/32, DD/32), 256>>>(wo + wofs, whi + OFF_WO(l),           DD, DD);
        tsplit_k<<<dim3(FF/32, DD/32), 256>>>(wf1 + (size_t)l*DD*FF, whi + OFF_F1(l), DD, FF);
        tsplit_k<<<dim3(DD/32, FF/32), 256>>>(wf2 + (size_t)l*FF*DD, whi + OFF_F2(l), FF, DD);
    }
    packb_k<<<(DEPTH*QS + 255)/256, 256>>>(bq, bk, bv, bqkv);
    cudaMemsetAsync(x, 0, (size_t)BMT * DD * sizeof(float));
    cudaMemsetAsync(mask, 0, BMT);
    scatter_k<<<dim3(NTRI, 3), 128>>>(triples, t2i, first, objtok, pred_emb, x, mask);

    // ---- transformer layers ----
    const dim3 gQKV(QS/BN, BMT/BM);   // (6, 512)
    const dim3 gD  (DD/BN, BMT/BM);   // (2, 512)
    const dim3 gF1 (FF/BN, BMT/BM);   // (8, 512)
    for (int l = 0; l < DEPTH; l++) {
        ln_k<<<BMT, 128>>>(x, ln1g + l*DD, ln1b + l*DD, ha);
        gemm2<false,true><<<gQKV, 256, GSM_TOTAL>>>(
            ha, whi + OFF_QKV(l), bqkv + l*QS, nullptr, nullptr, qkv, DD, QS);
        attn_k<<<dim3(NB, NH), 256>>>(qkv, mask, ata);
        gemm2<false,false><<<gD, 256, GSM_TOTAL>>>(
            ata, whi + OFF_WO(l), bo + l*DD, x, x, nullptr, DD, DD);
        ln_k<<<BMT, 128>>>(x, ln2g + l*DD, ln2b + l*DD, ha);
        gemm2<true,true><<<gF1, 256, GSM_TOTAL>>>(
            ha, whi + OFF_F1(l), bf1 + l*FF, nullptr, nullptr, ffa, DD, FF);
        float* cdst = (l == DEPTH - 1) ? outp : x;
        gemm2<false,false><<<gD, 256, GSM_TOTAL>>>(
            ffa, whi + OFF_F2(l), bf2 + l*DD, x, cdst, nullptr, FF, DD);
    }
}

// round 15
// speedup vs baseline: 1.2437x; 1.2437x over previous
#include <cuda_runtime.h>
#include <cuda_fp16.h>
#include <math.h>
#include <stdint.h>

// ---------------- problem constants ----------------
#define NB    1024
#define MT    64
#define DD    512
#define NH    8
#define HD    64
#define DEPTH 4
#define FF    2048
#define NOBJ  8192
#define NTRI  10240
#define BMT   (NB*MT)   // 65536 rows
#define QS    1536      // packed qkv row stride

// ---------------- static scratch ----------------
#define W_TOT 12845056
__device__ __half g_whi[W_TOT];
__device__ float  g_bqkv[DEPTH*QS];
__device__ float  g_x[BMT*DD];
__device__ __half g_ha [BMT*DD];
__device__ __half g_qkv[(size_t)BMT*QS];
__device__ __half g_ata[BMT*DD];
__device__ __half g_ffa[(size_t)BMT*FF];
__device__ __half g_bxa[NOBJ*DD];
__device__ float  g_objbase[NOBJ*DD];
__device__ float  g_objtok [NOBJ*DD];
__device__ unsigned char g_mask[BMT];
__device__ int    g_first[NB];

// weight pool offsets (elements)
#define OFF_BW2 0
#define LYR_STRIDE 3145728
#define OFF_L(l)   (262144 + (l)*LYR_STRIDE)
#define OFF_QKV(l) OFF_L(l)
#define OFF_WO(l)  (OFF_L(l)+786432)
#define OFF_F1(l)  (OFF_L(l)+1048576)
#define OFF_F2(l)  (OFF_L(l)+2097152)

__device__ __forceinline__ float gelu_f(float x) {
    return 0.5f * x * (1.0f + erff(x * 0.70710678118654752440f));
}
__device__ __forceinline__ uint32_t smem_u32(const void* p) {
    uint32_t a;
    asm("{ .reg .u64 t; cvta.to.shared.u64 t, %1; cvt.u32.u64 %0, t; }" : "=r"(a) : "l"(p));
    return a;
}

// ---------------- MMA primitives (family-wide, sm_80+) ----------------
__device__ __forceinline__ void ldm4(uint32_t* r, uint32_t addr) {
    asm volatile("ldmatrix.sync.aligned.m8n8.x4.shared.b16 {%0,%1,%2,%3}, [%4];"
        : "=r"(r[0]), "=r"(r[1]), "=r"(r[2]), "=r"(r[3]) : "r"(addr));
}
__device__ __forceinline__ void mma_f16(float* d, const uint32_t* a, const uint32_t* b) {
    asm volatile("mma.sync.aligned.m16n8k16.row.col.f32.f16.f16.f32 "
        "{%0,%1,%2,%3}, {%4,%5,%6,%7}, {%8,%9}, {%0,%1,%2,%3};"
        : "+f"(d[0]), "+f"(d[1]), "+f"(d[2]), "+f"(d[3])
        : "r"(a[0]), "r"(a[1]), "r"(a[2]), "r"(a[3]), "r"(b[0]), "r"(b[1]));
}
__device__ __forceinline__ void cpasync16(uint32_t sdst, const void* gsrc) {
    asm volatile("cp.async.cg.shared.global [%0], [%1], 16;" :: "r"(sdst), "l"(gsrc));
}
#define CP_COMMIT() asm volatile("cp.async.commit_group;" ::: "memory")
#define CP_WAIT1()  asm volatile("cp.async.wait_group 1;" ::: "memory")

// ---------------- fp16 single-term GEMM, 128x128 tile, BK=64, 2 CTAs/SM (R13 config) ----------------
#define BM 128
#define BN 128
#define BK 64
#define LDE 72          // padded smem row stride in elements (144 B)
#define A_OFF 0
#define B_OFF 18432
#define STG_SZ 36864
#define NSTG 3
#define GSM_TOTAL (NSTG*STG_SZ)   // 110592 B

template<bool GELU, bool HALFOUT>
__global__ void __launch_bounds__(256, 2) gemm2(
    const __half* __restrict__ A, const __half* __restrict__ B,
    const float* __restrict__ bias, const float* __restrict__ res,
    float* __restrict__ C, __half* __restrict__ Ch, int K, int ldc)
{
    extern __shared__ char sm[];
    const uint32_t smb = smem_u32(sm);
    const int tid  = threadIdx.x;
    const int lane = tid & 31;
    const int wid  = tid >> 5;
    const int wm   = (wid & 1) * 64;
    const int wn   = (wid >> 1) * 32;
    const int bn   = blockIdx.x * BN;
    const int bm   = blockIdx.y * BM;

    const int aRow = lane & 15;
    const int aK   = (lane >> 4) << 3;
    const int bRow = (lane & 7) + ((lane >> 4) << 3);
    const int bK   = ((lane >> 3) & 1) << 3;

    float d[4][4][4];
#pragma unroll
    for (int i = 0; i < 4; i++)
#pragma unroll
        for (int j = 0; j < 4; j++)
#pragma unroll
            for (int u = 0; u < 4; u++) d[i][j][u] = 0.f;

    const int NKT = K >> 6;

    auto load_stage = [&](int kt, int s) {
        const uint32_t stg = smb + (uint32_t)s * STG_SZ;
        const int k0 = kt << 6;
#pragma unroll
        for (int i = 0; i < 4; i++) {
            int id = tid + i * 256;
            int r = id >> 3, c = id & 7;
            uint32_t so = (uint32_t)(r * 144 + c * 16);
            cpasync16(stg + A_OFF + so, A + (size_t)(bm + r) * K + k0 + c * 8);
            cpasync16(stg + B_OFF + so, B + (size_t)(bn + r) * K + k0 + c * 8);
        }
    };

    auto compute = [&](int s) {
        const uint32_t stg = smb + (uint32_t)s * STG_SZ;
#pragma unroll
        for (int ks = 0; ks < 4; ks++) {
            const int kofs = ks * 16;
            uint32_t ah[4][4], bh[2][4];
#pragma unroll
            for (int mf = 0; mf < 4; mf++) {
                uint32_t ao = (uint32_t)((wm + mf*16 + aRow) * LDE + kofs + aK) * 2;
                ldm4(ah[mf], stg + A_OFF + ao);
            }
#pragma unroll
            for (int g = 0; g < 2; g++) {
                uint32_t bo = (uint32_t)((wn + g*16 + bRow) * LDE + kofs + bK) * 2;
                ldm4(bh[g], stg + B_OFF + bo);
            }
#pragma unroll
            for (int mf = 0; mf < 4; mf++)
#pragma unroll
                for (int nf = 0; nf < 4; nf++)
                    mma_f16(d[mf][nf], ah[mf], &bh[nf >> 1][(nf & 1) * 2]);
        }
    };

    load_stage(0, 0); CP_COMMIT();
    load_stage(1, 1); CP_COMMIT();
    for (int kt = 0; kt < NKT; kt++) {
        const int s = kt % 3;
        CP_WAIT1();
        __syncthreads();
        if (kt + 2 < NKT)
            load_stage(kt + 2, (kt + 2) % 3);
        CP_COMMIT();
        compute(s);
    }

#pragma unroll
    for (int mf = 0; mf < 4; mf++) {
        const int r0 = bm + wm + mf * 16 + (lane >> 2);
#pragma unroll
        for (int nf = 0; nf < 4; nf++) {
            const int c = bn + wn + nf * 8 + (lane & 3) * 2;
            float2 bv = *(const float2*)(bias + c);
            float v00 = d[mf][nf][0] + bv.x, v01 = d[mf][nf][1] + bv.y;
            float v10 = d[mf][nf][2] + bv.x, v11 = d[mf][nf][3] + bv.y;
            if (GELU) {
                v00 = gelu_f(v00); v01 = gelu_f(v01);
                v10 = gelu_f(v10); v11 = gelu_f(v11);
            }
            const size_t o0 = (size_t)r0 * ldc + c;
            const size_t o1 = (size_t)(r0 + 8) * ldc + c;
            if (HALFOUT) {
                *(half2*)(Ch + o0) = __floats2half2_rn(v00, v01);
                *(half2*)(Ch + o1) = __floats2half2_rn(v10, v11);
            } else {
                float2 w0 = make_float2(v00, v01);
                float2 w1 = make_float2(v10, v11);
                if (res) {
                    float2 rr0 = *(const float2*)(res + o0);
                    float2 rr1 = *(const float2*)(res + o1);
                    w0.x += rr0.x; w0.y += rr0.y;
                    w1.x += rr1.x; w1.y += rr1.y;
                }
                *(float2*)(C + o0) = w0;
                *(float2*)(C + o1) = w1;
            }
        }
    }
}

// ---------------- weight transpose + fp16 cast ----------------
__global__ void __launch_bounds__(256) tsplit_k(
    const float* __restrict__ W, __half* __restrict__ oh, int K, int N)
{
    __shared__ float tile[32][33];
    int tx = threadIdx.x & 31, ty = threadIdx.x >> 5;
    int n0 = blockIdx.x * 32, k0 = blockIdx.y * 32;
#pragma unroll
    for (int j = 0; j < 4; j++)
        tile[ty + j * 8][tx] = W[(size_t)(k0 + ty + j * 8) * N + n0 + tx];
    __syncthreads();
#pragma unroll
    for (int j = 0; j < 4; j++) {
        int n = n0 + ty + j * 8;
        int k = k0 + tx;
        oh[(size_t)n * K + k] = __float2half_rn(tile[tx][ty + j * 8]);
    }
}

// ---------------- pack q/k/v biases ----------------
__global__ void packb_k(const float* __restrict__ bq, const float* __restrict__ bk,
                        const float* __restrict__ bv, float* __restrict__ out)
{
    int i = blockIdx.x * blockDim.x + threadIdx.x;
    if (i >= DEPTH * QS) return;
    int l = i / QS, c = i % QS;
    float v;
    if (c < 512)       v = bq[l * 512 + c];
    else if (c < 1024) v = bk[l * 512 + c - 512];
    else               v = bv[l * 512 + c - 1024];
    out[i] = v;
}

// ---------------- LayerNorm -> fp16 ----------------
__global__ void __launch_bounds__(128) ln_k(
    const float* __restrict__ x, const float* __restrict__ g,
    const float* __restrict__ bvec, __half* __restrict__ oa)
{
    int row = blockIdx.x;
    const float* xr = x + (size_t)row * DD;
    int tid = threadIdx.x;
    float4 v = *(const float4*)(xr + tid * 4);
    float s  = v.x + v.y + v.z + v.w;
    float sq = v.x*v.x + v.y*v.y + v.z*v.z + v.w*v.w;
#pragma unroll
    for (int off = 16; off; off >>= 1) {
        s  += __shfl_xor_sync(0xffffffffu, s,  off);
        sq += __shfl_xor_sync(0xffffffffu, sq, off);
    }
    __shared__ float ss[4], ssq[4];
    int w = tid >> 5, l = tid & 31;
    if (l == 0) { ss[w] = s; ssq[w] = sq; }
    __syncthreads();
    s  = ss[0] + ss[1] + ss[2] + ss[3];
    sq = ssq[0] + ssq[1] + ssq[2] + ssq[3];
    float mean = s * (1.f / DD);
    float var  = sq * (1.f / DD) - mean * mean;
    float rstd = rsqrtf(var + 1e-5f);
    float4 gv = *(const float4*)(g    + tid * 4);
    float4 bb = *(const float4*)(bvec + tid * 4);
    float o0 = (v.x - mean) * rstd * gv.x + bb.x;
    float o1 = (v.y - mean) * rstd * gv.y + bb.y;
    float o2 = (v.z - mean) * rstd * gv.z + bb.z;
    float o3 = (v.w - mean) * rstd * gv.w + bb.w;
    size_t ob = (size_t)row * DD + tid * 4;
    *(half2*)(oa + ob)     = __floats2half2_rn(o0, o1);
    *(half2*)(oa + ob + 2) = __floats2half2_rn(o2, o3);
}

// ---------------- box MLP stage 1 -> fp16 ----------------
__global__ void __launch_bounds__(128) box_k(
    const float* __restrict__ boxes, const float* __restrict__ bw1,
    const float* __restrict__ bb1, const float* __restrict__ blg,
    const float* __restrict__ blb, __half* __restrict__ oa)
{
    int r = blockIdx.x;
    float b0 = boxes[r*4+0], b1 = boxes[r*4+1], b2 = boxes[r*4+2], b3 = boxes[r*4+3];
    int tid = threadIdx.x;
    int d0 = tid * 4;
    float4 w0 = *(const float4*)(bw1 + d0);
    float4 w1 = *(const float4*)(bw1 + 512  + d0);
    float4 w2 = *(const float4*)(bw1 + 1024 + d0);
    float4 w3 = *(const float4*)(bw1 + 1536 + d0);
    float4 bbv = *(const float4*)(bb1 + d0);
    float t[4];
    t[0] = bbv.x + b0*w0.x + b1*w1.x + b2*w2.x + b3*w3.x;
    t[1] = bbv.y + b0*w0.y + b1*w1.y + b2*w2.y + b3*w3.y;
    t[2] = bbv.z + b0*w0.z + b1*w1.z + b2*w2.z + b3*w3.z;
    t[3] = bbv.w + b0*w0.w + b1*w1.w + b2*w2.w + b3*w3.w;
    float s  = t[0]+t[1]+t[2]+t[3];
    float sq = t[0]*t[0]+t[1]*t[1]+t[2]*t[2]+t[3]*t[3];
#pragma unroll
    for (int off = 16; off; off >>= 1) {
        s  += __shfl_xor_sync(0xffffffffu, s,  off);
        sq += __shfl_xor_sync(0xffffffffu, sq, off);
    }
    __shared__ float ss[4], ssq[4];
    int w = tid >> 5, l = tid & 31;
    if (l == 0) { ss[w] = s; ssq[w] = sq; }
    __syncthreads();
    s  = ss[0] + ss[1] + ss[2] + ss[3];
    sq = ssq[0] + ssq[1] + ssq[2] + ssq[3];
    float mean = s * (1.f / DD);
    float var  = sq * (1.f / DD) - mean * mean;
    float rstd = rsqrtf(var + 1e-5f);
    float4 gv = *(const float4*)(blg + d0);
    float4 bv = *(const float4*)(blb + d0);
    float o0 = gelu_f((t[0]-mean)*rstd*gv.x + bv.x);
    float o1 = gelu_f((t[1]-mean)*rstd*gv.y + bv.y);
    float o2 = gelu_f((t[2]-mean)*rstd*gv.z + bv.z);
    float o3 = gelu_f((t[3]-mean)*rstd*gv.w + bv.w);
    size_t ob = (size_t)r * DD + d0;
    *(half2*)(oa + ob)     = __floats2half2_rn(o0, o1);
    *(half2*)(oa + ob + 2) = __floats2half2_rn(o2, o3);
}

// ---------------- gather obj embeddings ----------------
__global__ void __launch_bounds__(128) gather_k(
    const int* __restrict__ objs, const float* __restrict__ obj_emb,
    float* __restrict__ out)
{
    int r = blockIdx.x;
    int o = objs[r];
    float4 v = *(const float4*)(obj_emb + (size_t)o * DD + threadIdx.x * 4);
    *(float4*)(out + (size_t)r * DD + threadIdx.x * 4) = v;
}

// ---------------- first[i] ----------------
__global__ void first_k(const int* __restrict__ t2i, int* __restrict__ first)
{
    int i = blockIdx.x * blockDim.x + threadIdx.x;
    if (i >= NB) return;
    int lo = 0, hi = NTRI;
    while (lo < hi) {
        int mid = (lo + hi) >> 1;
        if (t2i[mid] < i) lo = mid + 1; else hi = mid;
    }
    first[i] = lo;
}

// ---------------- scatter ----------------
__global__ void __launch_bounds__(128) scatter_k(
    const int* __restrict__ triples, const int* __restrict__ t2i,
    const int* __restrict__ first, const float* __restrict__ objtok,
    const float* __restrict__ pred_emb, float* __restrict__ x,
    unsigned char* __restrict__ mask)
{
    int t = blockIdx.x;
    int j = blockIdx.y;
    int img = t2i[t];
    int pos = t - first[img];
    int slot = pos * 3 + j;
    if (slot >= MT) return;
    const float* src;
    if (j == 0)      src = objtok   + (size_t)triples[t*3+0] * DD;
    else if (j == 1) src = pred_emb + (size_t)triples[t*3+1] * DD;
    else             src = objtok   + (size_t)triples[t*3+2] * DD;
    float* dst = x + ((size_t)img * MT + slot) * DD;
    int tid = threadIdx.x;
    *(float4*)(dst + tid * 4) = *(const float4*)(src + tid * 4);
    if (tid == 0) mask[img * MT + slot] = 1;
}

// ---------------- attention via mma.sync: CTA = (batch, head pair) ----------------
#define ALD 72
#define HSZ (3*64*ALD)                 // halves per head (Q,K,Vt)
#define ATT_SMEM (2*HSZ*2 + 64)        // bytes: 2 heads * 3 mats * 64*72 halves + mask

__global__ void __launch_bounds__(256, 2) attn_k(
    const __half* __restrict__ qkv, const unsigned char* __restrict__ mask,
    __half* __restrict__ oa)
{
    extern __shared__ __half as[];
    unsigned char* smask = (unsigned char*)(as + 2 * HSZ);
    const int b = blockIdx.x, hp = blockIdx.y;
    const int tid = threadIdx.x, lane = tid & 31, wid = tid >> 5;
    const int hw = wid >> 2;     // head within pair
    const int wq = wid & 3;      // 16-row group
    const size_t qb0 = ((size_t)b * MT) * QS + (size_t)hp * 2 * HD;

    // ---- stage Q,K (row-major) for both heads: 2048 16B chunks ----
#pragma unroll
    for (int i = 0; i < 8; i++) {
        int idx = tid + i * 256;
        int c   = idx & 7;
        int row = (idx >> 3) & 63;
        int mat = (idx >> 9) & 1;     // 0=Q, 1=K
        int hh  = idx >> 10;          // head
        const uint4 v = *(const uint4*)(qkv + qb0 + (size_t)row * QS + hh * HD + mat * 512 + c * 8);
        *(uint4*)(as + hh * HSZ + mat * 64 * ALD + row * ALD + c * 8) = v;
    }
    // ---- stage V transposed: Vt[d][m] ----
#pragma unroll
    for (int i = 0; i < 16; i++) {
        int idx = tid + i * 256;
        int p   = idx & 31;           // half2 index: d = 2p
        int m   = (idx >> 5) & 63;
        int hh  = idx >> 11;
        half2 v2 = *(const half2*)(qkv + qb0 + (size_t)m * QS + hh * HD + 1024 + 2 * p);
        __half* Vt = as + hh * HSZ + 2 * 64 * ALD;
        Vt[(2 * p) * ALD + m]     = __low2half(v2);
        Vt[(2 * p + 1) * ALD + m] = __high2half(v2);
    }
    if (tid < 64) smask[tid] = mask[b * MT + tid];
    __syncthreads();

    const __half* Qh = as + hw * HSZ;
    const uint32_t qa = smem_u32(Qh);
    const uint32_t ka = qa + 64 * ALD * 2;
    const uint32_t va = qa + 2 * 64 * ALD * 2;

    const int aRow = lane & 15;
    const int aK   = (lane >> 4) << 3;
    const int bRow = (lane & 7) + ((lane >> 4) << 3);
    const int bK   = ((lane >> 3) & 1) << 3;

    // ---- S = Q @ K^T ----
    float s[8][4];
#pragma unroll
    for (int nf = 0; nf < 8; nf++)
#pragma unroll
        for (int u = 0; u < 4; u++) s[nf][u] = 0.f;
#pragma unroll
    for (int ks = 0; ks < 4; ks++) {
        uint32_t a[4], bb[4][4];
        ldm4(a, qa + (uint32_t)((16 * wq + aRow) * ALD + ks * 16 + aK) * 2);
#pragma unroll
        for (int g = 0; g < 4; g++)
            ldm4(bb[g], ka + (uint32_t)((16 * g + bRow) * ALD + ks * 16 + bK) * 2);
#pragma unroll
        for (int nf = 0; nf < 8; nf++)
            mma_f16(s[nf], a, &bb[nf >> 1][(nf & 1) * 2]);
    }

    // ---- mask + scale + softmax (rows r=16wq+lane>>2 and r+8) ----
    const int c0 = (lane & 3) * 2;
    float m0 = -1e30f, m1 = -1e30f;
#pragma unroll
    for (int nf = 0; nf < 8; nf++) {
        int cc = nf * 8 + c0;
        bool k0 = smask[cc] != 0, k1 = smask[cc + 1] != 0;
        s[nf][0] = k0 ? s[nf][0] * 0.125f : -1e9f;
        s[nf][1] = k1 ? s[nf][1] * 0.125f : -1e9f;
        s[nf][2] = k0 ? s[nf][2] * 0.125f : -1e9f;
        s[nf][3] = k1 ? s[nf][3] * 0.125f : -1e9f;
        m0 = fmaxf(m0, fmaxf(s[nf][0], s[nf][1]));
        m1 = fmaxf(m1, fmaxf(s[nf][2], s[nf][3]));
    }
#pragma unroll
    for (int off = 1; off <= 2; off <<= 1) {
        m0 = fmaxf(m0, __shfl_xor_sync(0xffffffffu, m0, off));
        m1 = fmaxf(m1, __shfl_xor_sync(0xffffffffu, m1, off));
    }
    float sum0 = 0.f, sum1 = 0.f;
#pragma unroll
    for (int nf = 0; nf < 8; nf++) {
        s[nf][0] = expf(s[nf][0] - m0); sum0 += s[nf][0];
        s[nf][1] = expf(s[nf][1] - m0); sum0 += s[nf][1];
        s[nf][2] = expf(s[nf][2] - m1); sum1 += s[nf][2];
        s[nf][3] = expf(s[nf][3] - m1); sum1 += s[nf][3];
    }
#pragma unroll
    for (int off = 1; off <= 2; off <<= 1) {
        sum0 += __shfl_xor_sync(0xffffffffu, sum0, off);
        sum1 += __shfl_xor_sync(0xffffffffu, sum1, off);
    }
    const float inv0 = 1.0f / sum0, inv1 = 1.0f / sum1;

    // ---- pack P into A fragments (k = seq) ----
    uint32_t pa[4][4];
#pragma unroll
    for (int j = 0; j < 4; j++) {
        half2 h0 = __floats2half2_rn(s[2*j][0] * inv0, s[2*j][1] * inv0);
        half2 h1 = __floats2half2_rn(s[2*j][2] * inv1, s[2*j][3] * inv1);
        half2 h2 = __floats2half2_rn(s[2*j+1][0] * inv0, s[2*j+1][1] * inv0);
        half2 h3 = __floats2half2_rn(s[2*j+1][2] * inv1, s[2*j+1][3] * inv1);
        pa[j][0] = *(uint32_t*)&h0;
        pa[j][1] = *(uint32_t*)&h1;
        pa[j][2] = *(uint32_t*)&h2;
        pa[j][3] = *(uint32_t*)&h3;
    }

    // ---- O = P @ V  (Vt layout [hd][seq] -> standard B path) ----
    float o[8][4];
#pragma unroll
    for (int nf = 0; nf < 8; nf++)
#pragma unroll
        for (int u = 0; u < 4; u++) o[nf][u] = 0.f;
#pragma unroll
    for (int j = 0; j < 4; j++) {
        uint32_t bv[4][4];
#pragma unroll
        for (int g = 0; g < 4; g++)
            ldm4(bv[g], va + (uint32_t)((16 * g + bRow) * ALD + j * 16 + bK) * 2);
#pragma unroll
        for (int nf = 0; nf < 8; nf++)
            mma_f16(o[nf], pa[j], &bv[nf >> 1][(nf & 1) * 2]);
    }

    // ---- store O (fp16) ----
    const int h = hp * 2 + hw;
    const size_t ob = ((size_t)b * MT) * DD + (size_t)h * HD;
    const int r0 = 16 * wq + (lane >> 2);
#pragma unroll
    for (int nf = 0; nf < 8; nf++) {
        int col = nf * 8 + c0;
        *(half2*)(oa + ob + (size_t)r0 * DD + col)       = __floats2half2_rn(o[nf][0], o[nf][1]);
        *(half2*)(oa + ob + (size_t)(r0 + 8) * DD + col) = __floats2half2_rn(o[nf][2], o[nf][3]);
    }
}

// ---------------- host launcher ----------------
extern "C" void kernel_launch(void* const* d_in, const int* in_sizes, int n_in,
                              void* d_out, int out_size)
{
    (void)in_sizes; (void)n_in; (void)out_size;
    const int*   objs    = (const int*)  d_in[0];
    const float* boxes   = (const float*)d_in[1];
    const int*   triples = (const int*)  d_in[2];
    const int*   t2i     = (const int*)  d_in[4];
    const float* obj_emb = (const float*)d_in[5];
    const float* pred_emb= (const float*)d_in[6];
    const float* bw1     = (const float*)d_in[7];
    const float* bb1     = (const float*)d_in[8];
    const float* blg     = (const float*)d_in[9];
    const float* blb     = (const float*)d_in[10];
    const float* bw2     = (const float*)d_in[11];
    const float* bb2     = (const float*)d_in[12];
    const float* ln1g    = (const float*)d_in[13];
    const float* ln1b    = (const float*)d_in[14];
    const float* wq      = (const float*)d_in[15];
    const float* bq      = (const float*)d_in[16];
    const float* wk      = (const float*)d_in[17];
    const float* bk      = (const float*)d_in[18];
    const float* wv      = (const float*)d_in[19];
    const float* bv      = (const float*)d_in[20];
    const float* wo      = (const float*)d_in[21];
    const float* bo      = (const float*)d_in[22];
    const float* ln2g    = (const float*)d_in[23];
    const float* ln2b    = (const float*)d_in[24];
    const float* wf1     = (const float*)d_in[25];
    const float* bf1     = (const float*)d_in[26];
    const float* wf2     = (const float*)d_in[27];
    const float* bf2     = (const float*)d_in[28];
    float* outp = (float*)d_out;

    float *x, *objbase, *objtok, *bqkv;
    __half *whi, *ha, *qkv, *ata, *ffa, *bxa;
    unsigned char* mask;
    int* first;
    cudaGetSymbolAddress((void**)&x,       g_x);
    cudaGetSymbolAddress((void**)&qkv,     g_qkv);
    cudaGetSymbolAddress((void**)&objbase, g_objbase);
    cudaGetSymbolAddress((void**)&objtok,  g_objtok);
    cudaGetSymbolAddress((void**)&mask,    g_mask);
    cudaGetSymbolAddress((void**)&first,   g_first);
    cudaGetSymbolAddress((void**)&bqkv,    g_bqkv);
    cudaGetSymbolAddress((void**)&whi,     g_whi);
    cudaGetSymbolAddress((void**)&ha,      g_ha);
    cudaGetSymbolAddress((void**)&ata,     g_ata);
    cudaGetSymbolAddress((void**)&ffa,     g_ffa);
    cudaGetSymbolAddress((void**)&bxa,     g_bxa);

    cudaFuncSetAttribute(gemm2<false,false>, cudaFuncAttributeMaxDynamicSharedMemorySize, GSM_TOTAL);
    cudaFuncSetAttribute(gemm2<false,true>,  cudaFuncAttributeMaxDynamicSharedMemorySize, GSM_TOTAL);
    cudaFuncSetAttribute(gemm2<true,true>,   cudaFuncAttributeMaxDynamicSharedMemorySize, GSM_TOTAL);
    cudaFuncSetAttribute(attn_k,             cudaFuncAttributeMaxDynamicSharedMemorySize, ATT_SMEM);

    // launch order: #3 (0-based) is the objtok GEMM -> that's what ncu profiles
    tsplit_k<<<dim3(DD/32, DD/32), 256>>>(bw2, whi + OFF_BW2, DD, DD);                  // 0
    box_k<<<NOBJ, 128>>>(boxes, bw1, bb1, blg, blb, bxa);                               // 1
    gather_k<<<NOBJ, 128>>>(objs, obj_emb, objbase);                                    // 2
    gemm2<false,false><<<dim3(DD/BN, NOBJ/BM), 256, GSM_TOTAL>>>(                       // 3
        bxa, whi + OFF_BW2, bb2, objbase, objtok, nullptr, DD, DD);
    first_k<<<(NB + 127)/128, 128>>>(t2i, first);                                       // 4

    // remaining weight prep
    for (int l = 0; l < DEPTH; l++) {
        size_t wofs = (size_t)l * DD * DD;
        tsplit_k<<<dim3(DD/32, DD/32), 256>>>(wq + wofs, whi + OFF_QKV(l),          DD, DD);
        tsplit_k<<<dim3(DD/32, DD/32), 256>>>(wk + wofs, whi + OFF_QKV(l) + 262144, DD, DD);
        tsplit_k<<<dim3(DD/32, DD/32), 256>>>(wv + wofs, whi + OFF_QKV(l) + 524288, DD, DD);
        tsplit_k<<<dim3(DD/32, DD/32), 256>>>(wo + wofs, whi + OFF_WO(l),           DD, DD);
        tsplit_k<<<dim3(FF/32, DD/32), 256>>>(wf1 + (size_t)l*DD*FF, whi + OFF_F1(l), DD, FF);
        tsplit_k<<<dim3(DD/32, FF/32), 256>>>(wf2 + (size_t)l*FF*DD, whi + OFF_F2(l), FF, DD);
    }
    packb_k<<<(DEPTH*QS + 255)/256, 256>>>(bq, bk, bv, bqkv);
    cudaMemsetAsync(x, 0, (size_t)BMT * DD * sizeof(float));
    cudaMemsetAsync(mask, 0, BMT);
    scatter_k<<<dim3(NTRI, 3), 128>>>(triples, t2i, first, objtok, pred_emb, x, mask);

    // ---- transformer layers ----
    const dim3 gQKV(QS/BN, BMT/BM);   // (12, 512)
    const dim3 gD  (DD/BN, BMT/BM);   // (4, 512)
    const dim3 gF1 (FF/BN, BMT/BM);   // (16, 512)
    for (int l = 0; l < DEPTH; l++) {
        ln_k<<<BMT, 128>>>(x, ln1g + l*DD, ln1b + l*DD, ha);
        gemm2<false,true><<<gQKV, 256, GSM_TOTAL>>>(
            ha, whi + OFF_QKV(l), bqkv + l*QS, nullptr, nullptr, qkv, DD, QS);
        attn_k<<<dim3(NB, NH/2), 256, ATT_SMEM>>>(qkv, mask, ata);
        gemm2<false,false><<<gD, 256, GSM_TOTAL>>>(
            ata, whi + OFF_WO(l), bo + l*DD, x, x, nullptr, DD, DD);
        ln_k<<<BMT, 128>>>(x, ln2g + l*DD, ln2b + l*DD, ha);
        gemm2<true,true><<<gF1, 256, GSM_TOTAL>>>(
            ha, whi + OFF_F1(l), bf1 + l*FF, nullptr, nullptr, ffa, DD, FF);
        float* cdst = (l == DEPTH - 1) ? outp : x;
        gemm2<false,false><<<gD, 256, GSM_TOTAL>>>(
            ffa, whi + OFF_F2(l), bf2 + l*DD, x, cdst, nullptr, FF, DD);
    }
}

// round 16
// speedup vs baseline: 1.2668x; 1.0185x over previous
#include <cuda_runtime.h>
#include <cuda_fp16.h>
#include <math.h>
#include <stdint.h>

// ---------------- problem constants ----------------
#define NB    1024
#define MT    64
#define DD    512
#define NH    8
#define HD    64
#define DEPTH 4
#define FF    2048
#define NOBJ  8192
#define NTRI  10240
#define BMT   (NB*MT)   // 65536 rows
#define QS    1536      // packed qkv row stride

// ---------------- static scratch ----------------
#define W_TOT 12845056
__device__ __half g_whi[W_TOT];
__device__ float  g_bqkv[DEPTH*QS];
__device__ __half g_x[BMT*DD];              // fp16 residual stream
__device__ __half g_ha [BMT*DD];
__device__ __half g_qkv[(size_t)BMT*QS];
__device__ __half g_ata[BMT*DD];
__device__ __half g_ffa[(size_t)BMT*FF];
__device__ __half g_bxa[NOBJ*DD];
__device__ float  g_objbase[NOBJ*DD];
__device__ float  g_objtok [NOBJ*DD];
__device__ unsigned char g_mask[BMT];
__device__ int    g_first[NB];

// weight pool offsets (elements)
#define OFF_BW2 0
#define LYR_STRIDE 3145728
#define OFF_L(l)   (262144 + (l)*LYR_STRIDE)
#define OFF_QKV(l) OFF_L(l)
#define OFF_WO(l)  (OFF_L(l)+786432)
#define OFF_F1(l)  (OFF_L(l)+1048576)
#define OFF_F2(l)  (OFF_L(l)+2097152)

__device__ __forceinline__ float gelu_f(float x) {
    return 0.5f * x * (1.0f + erff(x * 0.70710678118654752440f));
}
__device__ __forceinline__ uint32_t smem_u32(const void* p) {
    uint32_t a;
    asm("{ .reg .u64 t; cvta.to.shared.u64 t, %1; cvt.u32.u64 %0, t; }" : "=r"(a) : "l"(p));
    return a;
}

// ---------------- MMA primitives (family-wide, sm_80+) ----------------
__device__ __forceinline__ void ldm4(uint32_t* r, uint32_t addr) {
    asm volatile("ldmatrix.sync.aligned.m8n8.x4.shared.b16 {%0,%1,%2,%3}, [%4];"
        : "=r"(r[0]), "=r"(r[1]), "=r"(r[2]), "=r"(r[3]) : "r"(addr));
}
__device__ __forceinline__ void mma_f16(float* d, const uint32_t* a, const uint32_t* b) {
    asm volatile("mma.sync.aligned.m16n8k16.row.col.f32.f16.f16.f32 "
        "{%0,%1,%2,%3}, {%4,%5,%6,%7}, {%8,%9}, {%0,%1,%2,%3};"
        : "+f"(d[0]), "+f"(d[1]), "+f"(d[2]), "+f"(d[3])
        : "r"(a[0]), "r"(a[1]), "r"(a[2]), "r"(a[3]), "r"(b[0]), "r"(b[1]));
}
__device__ __forceinline__ void cpasync16(uint32_t sdst, const void* gsrc) {
    asm volatile("cp.async.cg.shared.global [%0], [%1], 16;" :: "r"(sdst), "l"(gsrc));
}
#define CP_COMMIT() asm volatile("cp.async.commit_group;" ::: "memory")
#define CP_WAIT1()  asm volatile("cp.async.wait_group 1;" ::: "memory")

// ---------------- fp16 single-term GEMM, 128x128 tile, BK=64, 2 CTAs/SM ----------------
// RES: 0=none, 1=fp32 res, 2=fp16 res.  OUT: 0=fp32, 1=fp16.
#define BM 128
#define BN 128
#define BK 64
#define LDE 72
#define A_OFF 0
#define B_OFF 18432
#define STG_SZ 36864
#define NSTG 3
#define GSM_TOTAL (NSTG*STG_SZ)   // 110592 B

template<bool GELU, int RES, int OUT>
__global__ void __launch_bounds__(256, 2) gemm2(
    const __half* __restrict__ A, const __half* __restrict__ B,
    const float* __restrict__ bias, const void* __restrict__ resv,
    void* __restrict__ Cv, int K, int ldc)
{
    extern __shared__ char sm[];
    const uint32_t smb = smem_u32(sm);
    const int tid  = threadIdx.x;
    const int lane = tid & 31;
    const int wid  = tid >> 5;
    const int wm   = (wid & 1) * 64;
    const int wn   = (wid >> 1) * 32;
    const int bn   = blockIdx.x * BN;
    const int bm   = blockIdx.y * BM;

    const int aRow = lane & 15;
    const int aK   = (lane >> 4) << 3;
    const int bRow = (lane & 7) + ((lane >> 4) << 3);
    const int bK   = ((lane >> 3) & 1) << 3;

    float d[4][4][4];
#pragma unroll
    for (int i = 0; i < 4; i++)
#pragma unroll
        for (int j = 0; j < 4; j++)
#pragma unroll
            for (int u = 0; u < 4; u++) d[i][j][u] = 0.f;

    const int NKT = K >> 6;

    auto load_stage = [&](int kt, int s) {
        const uint32_t stg = smb + (uint32_t)s * STG_SZ;
        const int k0 = kt << 6;
#pragma unroll
        for (int i = 0; i < 4; i++) {
            int id = tid + i * 256;
            int r = id >> 3, c = id & 7;
            uint32_t so = (uint32_t)(r * 144 + c * 16);
            cpasync16(stg + A_OFF + so, A + (size_t)(bm + r) * K + k0 + c * 8);
            cpasync16(stg + B_OFF + so, B + (size_t)(bn + r) * K + k0 + c * 8);
        }
    };

    auto compute = [&](int s) {
        const uint32_t stg = smb + (uint32_t)s * STG_SZ;
#pragma unroll
        for (int ks = 0; ks < 4; ks++) {
            const int kofs = ks * 16;
            uint32_t ah[4][4], bh[2][4];
#pragma unroll
            for (int mf = 0; mf < 4; mf++) {
                uint32_t ao = (uint32_t)((wm + mf*16 + aRow) * LDE + kofs + aK) * 2;
                ldm4(ah[mf], stg + A_OFF + ao);
            }
#pragma unroll
            for (int g = 0; g < 2; g++) {
                uint32_t bo = (uint32_t)((wn + g*16 + bRow) * LDE + kofs + bK) * 2;
                ldm4(bh[g], stg + B_OFF + bo);
            }
#pragma unroll
            for (int mf = 0; mf < 4; mf++)
#pragma unroll
                for (int nf = 0; nf < 4; nf++)
                    mma_f16(d[mf][nf], ah[mf], &bh[nf >> 1][(nf & 1) * 2]);
        }
    };

    load_stage(0, 0); CP_COMMIT();
    load_stage(1, 1); CP_COMMIT();
    for (int kt = 0; kt < NKT; kt++) {
        const int s = kt % 3;
        CP_WAIT1();
        __syncthreads();
        if (kt + 2 < NKT)
            load_stage(kt + 2, (kt + 2) % 3);
        CP_COMMIT();
        compute(s);
    }

#pragma unroll
    for (int mf = 0; mf < 4; mf++) {
        const int r0 = bm + wm + mf * 16 + (lane >> 2);
#pragma unroll
        for (int nf = 0; nf < 4; nf++) {
            const int c = bn + wn + nf * 8 + (lane & 3) * 2;
            float2 bv = *(const float2*)(bias + c);
            float2 w0 = make_float2(d[mf][nf][0] + bv.x, d[mf][nf][1] + bv.y);
            float2 w1 = make_float2(d[mf][nf][2] + bv.x, d[mf][nf][3] + bv.y);
            if (GELU) {
                w0.x = gelu_f(w0.x); w0.y = gelu_f(w0.y);
                w1.x = gelu_f(w1.x); w1.y = gelu_f(w1.y);
            }
            const size_t o0 = (size_t)r0 * ldc + c;
            const size_t o1 = (size_t)(r0 + 8) * ldc + c;
            if (RES == 1) {
                const float* res = (const float*)resv;
                float2 rr0 = *(const float2*)(res + o0);
                float2 rr1 = *(const float2*)(res + o1);
                w0.x += rr0.x; w0.y += rr0.y;
                w1.x += rr1.x; w1.y += rr1.y;
            } else if (RES == 2) {
                const __half* res = (const __half*)resv;
                float2 rr0 = __half22float2(*(const half2*)(res + o0));
                float2 rr1 = __half22float2(*(const half2*)(res + o1));
                w0.x += rr0.x; w0.y += rr0.y;
                w1.x += rr1.x; w1.y += rr1.y;
            }
            if (OUT == 0) {
                float* C = (float*)Cv;
                *(float2*)(C + o0) = w0;
                *(float2*)(C + o1) = w1;
            } else {
                __half* C = (__half*)Cv;
                *(half2*)(C + o0) = __floats2half2_rn(w0.x, w0.y);
                *(half2*)(C + o1) = __floats2half2_rn(w1.x, w1.y);
            }
        }
    }
}

// ---------------- weight transpose + fp16 cast (z-batched) ----------------
__global__ void __launch_bounds__(256) tsplit_k(
    const float* __restrict__ Wb, __half* __restrict__ ohb, int K, int N,
    size_t wz, size_t qz)
{
    const float* W = Wb + blockIdx.z * wz;
    __half* oh = ohb + blockIdx.z * qz;
    __shared__ float tile[32][33];
    int tx = threadIdx.x & 31, ty = threadIdx.x >> 5;
    int n0 = blockIdx.x * 32, k0 = blockIdx.y * 32;
#pragma unroll
    for (int j = 0; j < 4; j++)
        tile[ty + j * 8][tx] = W[(size_t)(k0 + ty + j * 8) * N + n0 + tx];
    __syncthreads();
#pragma unroll
    for (int j = 0; j < 4; j++) {
        int n = n0 + ty + j * 8;
        int k = k0 + tx;
        oh[(size_t)n * K + k] = __float2half_rn(tile[tx][ty + j * 8]);
    }
}

// ---------------- pack q/k/v biases ----------------
__global__ void packb_k(const float* __restrict__ bq, const float* __restrict__ bk,
                        const float* __restrict__ bv, float* __restrict__ out)
{
    int i = blockIdx.x * blockDim.x + threadIdx.x;
    if (i >= DEPTH * QS) return;
    int l = i / QS, c = i % QS;
    float v;
    if (c < 512)       v = bq[l * 512 + c];
    else if (c < 1024) v = bk[l * 512 + c - 512];
    else               v = bv[l * 512 + c - 1024];
    out[i] = v;
}

// ---------------- LayerNorm: fp16 in -> fp16 out ----------------
__global__ void __launch_bounds__(128) ln_k(
    const __half* __restrict__ x, const float* __restrict__ g,
    const float* __restrict__ bvec, __half* __restrict__ oa)
{
    int row = blockIdx.x;
    const __half* xr = x + (size_t)row * DD;
    int tid = threadIdx.x;
    half2 h01 = *(const half2*)(xr + tid * 4);
    half2 h23 = *(const half2*)(xr + tid * 4 + 2);
    float2 f01 = __half22float2(h01), f23 = __half22float2(h23);
    float vx = f01.x, vy = f01.y, vz = f23.x, vw = f23.y;
    float s  = vx + vy + vz + vw;
    float sq = vx*vx + vy*vy + vz*vz + vw*vw;
#pragma unroll
    for (int off = 16; off; off >>= 1) {
        s  += __shfl_xor_sync(0xffffffffu, s,  off);
        sq += __shfl_xor_sync(0xffffffffu, sq, off);
    }
    __shared__ float ss[4], ssq[4];
    int w = tid >> 5, l = tid & 31;
    if (l == 0) { ss[w] = s; ssq[w] = sq; }
    __syncthreads();
    s  = ss[0] + ss[1] + ss[2] + ss[3];
    sq = ssq[0] + ssq[1] + ssq[2] + ssq[3];
    float mean = s * (1.f / DD);
    float var  = sq * (1.f / DD) - mean * mean;
    float rstd = rsqrtf(var + 1e-5f);
    float4 gv = *(const float4*)(g    + tid * 4);
    float4 bb = *(const float4*)(bvec + tid * 4);
    float o0 = (vx - mean) * rstd * gv.x + bb.x;
    float o1 = (vy - mean) * rstd * gv.y + bb.y;
    float o2 = (vz - mean) * rstd * gv.z + bb.z;
    float o3 = (vw - mean) * rstd * gv.w + bb.w;
    size_t ob = (size_t)row * DD + tid * 4;
    *(half2*)(oa + ob)     = __floats2half2_rn(o0, o1);
    *(half2*)(oa + ob + 2) = __floats2half2_rn(o2, o3);
}

// ---------------- box MLP stage 1 -> fp16 ----------------
__global__ void __launch_bounds__(128) box_k(
    const float* __restrict__ boxes, const float* __restrict__ bw1,
    const float* __restrict__ bb1, const float* __restrict__ blg,
    const float* __restrict__ blb, __half* __restrict__ oa)
{
    int r = blockIdx.x;
    float b0 = boxes[r*4+0], b1 = boxes[r*4+1], b2 = boxes[r*4+2], b3 = boxes[r*4+3];
    int tid = threadIdx.x;
    int d0 = tid * 4;
    float4 w0 = *(const float4*)(bw1 + d0);
    float4 w1 = *(const float4*)(bw1 + 512  + d0);
    float4 w2 = *(const float4*)(bw1 + 1024 + d0);
    float4 w3 = *(const float4*)(bw1 + 1536 + d0);
    float4 bbv = *(const float4*)(bb1 + d0);
    float t[4];
    t[0] = bbv.x + b0*w0.x + b1*w1.x + b2*w2.x + b3*w3.x;
    t[1] = bbv.y + b0*w0.y + b1*w1.y + b2*w2.y + b3*w3.y;
    t[2] = bbv.z + b0*w0.z + b1*w1.z + b2*w2.z + b3*w3.z;
    t[3] = bbv.w + b0*w0.w + b1*w1.w + b2*w2.w + b3*w3.w;
    float s  = t[0]+t[1]+t[2]+t[3];
    float sq = t[0]*t[0]+t[1]*t[1]+t[2]*t[2]+t[3]*t[3];
#pragma unroll
    for (int off = 16; off; off >>= 1) {
        s  += __shfl_xor_sync(0xffffffffu, s,  off);
        sq += __shfl_xor_sync(0xffffffffu, sq, off);
    }
    __shared__ float ss[4], ssq[4];
    int w = tid >> 5, l = tid & 31;
    if (l == 0) { ss[w] = s; ssq[w] = sq; }
    __syncthreads();
    s  = ss[0] + ss[1] + ss[2] + ss[3];
    sq = ssq[0] + ssq[1] + ssq[2] + ssq[3];
    float mean = s * (1.f / DD);
    float var  = sq * (1.f / DD) - mean * mean;
    float rstd = rsqrtf(var + 1e-5f);
    float4 gv = *(const float4*)(blg + d0);
    float4 bv = *(const float4*)(blb + d0);
    float o0 = gelu_f((t[0]-mean)*rstd*gv.x + bv.x);
    float o1 = gelu_f((t[1]-mean)*rstd*gv.y + bv.y);
    float o2 = gelu_f((t[2]-mean)*rstd*gv.z + bv.z);
    float o3 = gelu_f((t[3]-mean)*rstd*gv.w + bv.w);
    size_t ob = (size_t)r * DD + d0;
    *(half2*)(oa + ob)     = __floats2half2_rn(o0, o1);
    *(half2*)(oa + ob + 2) = __floats2half2_rn(o2, o3);
}

// ---------------- gather obj embeddings ----------------
__global__ void __launch_bounds__(128) gather_k(
    const int* __restrict__ objs, const float* __restrict__ obj_emb,
    float* __restrict__ out)
{
    int r = blockIdx.x;
    int o = objs[r];
    float4 v = *(const float4*)(obj_emb + (size_t)o * DD + threadIdx.x * 4);
    *(float4*)(out + (size_t)r * DD + threadIdx.x * 4) = v;
}

// ---------------- first[i] ----------------
__global__ void first_k(const int* __restrict__ t2i, int* __restrict__ first)
{
    int i = blockIdx.x * blockDim.x + threadIdx.x;
    if (i >= NB) return;
    int lo = 0, hi = NTRI;
    while (lo < hi) {
        int mid = (lo + hi) >> 1;
        if (t2i[mid] < i) lo = mid + 1; else hi = mid;
    }
    first[i] = lo;
}

// ---------------- scatter: fp32 tokens -> fp16 x ----------------
__global__ void __launch_bounds__(128) scatter_k(
    const int* __restrict__ triples, const int* __restrict__ t2i,
    const int* __restrict__ first, const float* __restrict__ objtok,
    const float* __restrict__ pred_emb, __half* __restrict__ x,
    unsigned char* __restrict__ mask)
{
    int t = blockIdx.x;
    int j = blockIdx.y;
    int img = t2i[t];
    int pos = t - first[img];
    int slot = pos * 3 + j;
    if (slot >= MT) return;
    const float* src;
    if (j == 0)      src = objtok   + (size_t)triples[t*3+0] * DD;
    else if (j == 1) src = pred_emb + (size_t)triples[t*3+1] * DD;
    else             src = objtok   + (size_t)triples[t*3+2] * DD;
    __half* dst = x + ((size_t)img * MT + slot) * DD;
    int tid = threadIdx.x;
    float4 v = *(const float4*)(src + tid * 4);
    *(half2*)(dst + tid * 4)     = __floats2half2_rn(v.x, v.y);
    *(half2*)(dst + tid * 4 + 2) = __floats2half2_rn(v.z, v.w);
    if (tid == 0) mask[img * MT + slot] = 1;
}

// ---------------- attention via mma.sync: CTA = (batch, head pair) ----------------
#define ALD 72
#define HSZ (3*64*ALD)
#define ATT_SMEM (2*HSZ*2 + 64)

__global__ void __launch_bounds__(256, 2) attn_k(
    const __half* __restrict__ qkv, const unsigned char* __restrict__ mask,
    __half* __restrict__ oa)
{
    extern __shared__ __half as[];
    unsigned char* smask = (unsigned char*)(as + 2 * HSZ);
    const int b = blockIdx.x, hp = blockIdx.y;
    const int tid = threadIdx.x, lane = tid & 31, wid = tid >> 5;
    const int hw = wid >> 2;
    const int wq = wid & 3;
    const size_t qb0 = ((size_t)b * MT) * QS + (size_t)hp * 2 * HD;

#pragma unroll
    for (int i = 0; i < 8; i++) {
        int idx = tid + i * 256;
        int c   = idx & 7;
        int row = (idx >> 3) & 63;
        int mat = (idx >> 9) & 1;
        int hh  = idx >> 10;
        const uint4 v = *(const uint4*)(qkv + qb0 + (size_t)row * QS + hh * HD + mat * 512 + c * 8);
        *(uint4*)(as + hh * HSZ + mat * 64 * ALD + row * ALD + c * 8) = v;
    }
#pragma unroll
    for (int i = 0; i < 16; i++) {
        int idx = tid + i * 256;
        int p   = idx & 31;
        int m   = (idx >> 5) & 63;
        int hh  = idx >> 11;
        half2 v2 = *(const half2*)(qkv + qb0 + (size_t)m * QS + hh * HD + 1024 + 2 * p);
        __half* Vt = as + hh * HSZ + 2 * 64 * ALD;
        Vt[(2 * p) * ALD + m]     = __low2half(v2);
        Vt[(2 * p + 1) * ALD + m] = __high2half(v2);
    }
    if (tid < 64) smask[tid] = mask[b * MT + tid];
    __syncthreads();

    const __half* Qh = as + hw * HSZ;
    const uint32_t qa = smem_u32(Qh);
    const uint32_t ka = qa + 64 * ALD * 2;
    const uint32_t va = qa + 2 * 64 * ALD * 2;

    const int aRow = lane & 15;
    const int aK   = (lane >> 4) << 3;
    const int bRow = (lane & 7) + ((lane >> 4) << 3);
    const int bK   = ((lane >> 3) & 1) << 3;

    float s[8][4];
#pragma unroll
    for (int nf = 0; nf < 8; nf++)
#pragma unroll
        for (int u = 0; u < 4; u++) s[nf][u] = 0.f;
#pragma unroll
    for (int ks = 0; ks < 4; ks++) {
        uint32_t a[4], bb[4][4];
        ldm4(a, qa + (uint32_t)((16 * wq + aRow) * ALD + ks * 16 + aK) * 2);
#pragma unroll
        for (int g = 0; g < 4; g++)
            ldm4(bb[g], ka + (uint32_t)((16 * g + bRow) * ALD + ks * 16 + bK) * 2);
#pragma unroll
        for (int nf = 0; nf < 8; nf++)
            mma_f16(s[nf], a, &bb[nf >> 1][(nf & 1) * 2]);
    }

    const int c0 = (lane & 3) * 2;
    float m0 = -1e30f, m1 = -1e30f;
#pragma unroll
    for (int nf = 0; nf < 8; nf++) {
        int cc = nf * 8 + c0;
        bool k0 = smask[cc] != 0, k1 = smask[cc + 1] != 0;
        s[nf][0] = k0 ? s[nf][0] * 0.125f : -1e9f;
        s[nf][1] = k1 ? s[nf][1] * 0.125f : -1e9f;
        s[nf][2] = k0 ? s[nf][2] * 0.125f : -1e9f;
        s[nf][3] = k1 ? s[nf][3] * 0.125f : -1e9f;
        m0 = fmaxf(m0, fmaxf(s[nf][0], s[nf][1]));
        m1 = fmaxf(m1, fmaxf(s[nf][2], s[nf][3]));
    }
#pragma unroll
    for (int off = 1; off <= 2; off <<= 1) {
        m0 = fmaxf(m0, __shfl_xor_sync(0xffffffffu, m0, off));
        m1 = fmaxf(m1, __shfl_xor_sync(0xffffffffu, m1, off));
    }
    float sum0 = 0.f, sum1 = 0.f;
#pragma unroll
    for (int nf = 0; nf < 8; nf++) {
        s[nf][0] = expf(s[nf][0] - m0); sum0 += s[nf][0];
        s[nf][1] = expf(s[nf][1] - m0); sum0 += s[nf][1];
        s[nf][2] = expf(s[nf][2] - m1); sum1 += s[nf][2];
        s[nf][3] = expf(s[nf][3] - m1); sum1 += s[nf][3];
    }
#pragma unroll
    for (int off = 1; off <= 2; off <<= 1) {
        sum0 += __shfl_xor_sync(0xffffffffu, sum0, off);
        sum1 += __shfl_xor_sync(0xffffffffu, sum1, off);
    }
    const float inv0 = 1.0f / sum0, inv1 = 1.0f / sum1;

    uint32_t pa[4][4];
#pragma unroll
    for (int j = 0; j < 4; j++) {
        half2 h0 = __floats2half2_rn(s[2*j][0] * inv0, s[2*j][1] * inv0);
        half2 h1 = __floats2half2_rn(s[2*j][2] * inv1, s[2*j][3] * inv1);
        half2 h2 = __floats2half2_rn(s[2*j+1][0] * inv0, s[2*j+1][1] * inv0);
        half2 h3 = __floats2half2_rn(s[2*j+1][2] * inv1, s[2*j+1][3] * inv1);
        pa[j][0] = *(uint32_t*)&h0;
        pa[j][1] = *(uint32_t*)&h1;
        pa[j][2] = *(uint32_t*)&h2;
        pa[j][3] = *(uint32_t*)&h3;
    }

    float o[8][4];
#pragma unroll
    for (int nf = 0; nf < 8; nf++)
#pragma unroll
        for (int u = 0; u < 4; u++) o[nf][u] = 0.f;
#pragma unroll
    for (int j = 0; j < 4; j++) {
        uint32_t bv[4][4];
#pragma unroll
        for (int g = 0; g < 4; g++)
            ldm4(bv[g], va + (uint32_t)((16 * g + bRow) * ALD + j * 16 + bK) * 2);
#pragma unroll
        for (int nf = 0; nf < 8; nf++)
            mma_f16(o[nf], pa[j], &bv[nf >> 1][(nf & 1) * 2]);
    }

    const int h = hp * 2 + hw;
    const size_t ob = ((size_t)b * MT) * DD + (size_t)h * HD;
    const int r0 = 16 * wq + (lane >> 2);
#pragma unroll
    for (int nf = 0; nf < 8; nf++) {
        int col = nf * 8 + c0;
        *(half2*)(oa + ob + (size_t)r0 * DD + col)       = __floats2half2_rn(o[nf][0], o[nf][1]);
        *(half2*)(oa + ob + (size_t)(r0 + 8) * DD + col) = __floats2half2_rn(o[nf][2], o[nf][3]);
    }
}

// ---------------- host launcher ----------------
extern "C" void kernel_launch(void* const* d_in, const int* in_sizes, int n_in,
                              void* d_out, int out_size)
{
    (void)in_sizes; (void)n_in; (void)out_size;
    const int*   objs    = (const int*)  d_in[0];
    const float* boxes   = (const float*)d_in[1];
    const int*   triples = (const int*)  d_in[2];
    const int*   t2i     = (const int*)  d_in[4];
    const float* obj_emb = (const float*)d_in[5];
    const float* pred_emb= (const float*)d_in[6];
    const float* bw1     = (const float*)d_in[7];
    const float* bb1     = (const float*)d_in[8];
    const float* blg     = (const float*)d_in[9];
    const float* blb     = (const float*)d_in[10];
    const float* bw2     = (const float*)d_in[11];
    const float* bb2     = (const float*)d_in[12];
    const float* ln1g    = (const float*)d_in[13];
    const float* ln1b    = (const float*)d_in[14];
    const float* wq      = (const float*)d_in[15];
    const float* bq      = (const float*)d_in[16];
    const float* wk      = (const float*)d_in[17];
    const float* bk      = (const float*)d_in[18];
    const float* wv      = (const float*)d_in[19];
    const float* bv      = (const float*)d_in[20];
    const float* wo      = (const float*)d_in[21];
    const float* bo      = (const float*)d_in[22];
    const float* ln2g    = (const float*)d_in[23];
    const float* ln2b    = (const float*)d_in[24];
    const float* wf1     = (const float*)d_in[25];
    const float* bf1     = (const float*)d_in[26];
    const float* wf2     = (const float*)d_in[27];
    const float* bf2     = (const float*)d_in[28];
    float* outp = (float*)d_out;

    float *objbase, *objtok, *bqkv;
    __half *whi, *x, *ha, *qkv, *ata, *ffa, *bxa;
    unsigned char* mask;
    int* first;
    cudaGetSymbolAddress((void**)&x,       g_x);
    cudaGetSymbolAddress((void**)&qkv,     g_qkv);
    cudaGetSymbolAddress((void**)&objbase, g_objbase);
    cudaGetSymbolAddress((void**)&objtok,  g_objtok);
    cudaGetSymbolAddress((void**)&mask,    g_mask);
    cudaGetSymbolAddress((void**)&first,   g_first);
    cudaGetSymbolAddress((void**)&bqkv,    g_bqkv);
    cudaGetSymbolAddress((void**)&whi,     g_whi);
    cudaGetSymbolAddress((void**)&ha,      g_ha);
    cudaGetSymbolAddress((void**)&ata,     g_ata);
    cudaGetSymbolAddress((void**)&ffa,     g_ffa);
    cudaGetSymbolAddress((void**)&bxa,     g_bxa);

    cudaFuncSetAttribute(gemm2<false,1,0>, cudaFuncAttributeMaxDynamicSharedMemorySize, GSM_TOTAL);
    cudaFuncSetAttribute(gemm2<false,0,1>, cudaFuncAttributeMaxDynamicSharedMemorySize, GSM_TOTAL);
    cudaFuncSetAttribute(gemm2<false,2,1>, cudaFuncAttributeMaxDynamicSharedMemorySize, GSM_TOTAL);
    cudaFuncSetAttribute(gemm2<true,0,1>,  cudaFuncAttributeMaxDynamicSharedMemorySize, GSM_TOTAL);
    cudaFuncSetAttribute(gemm2<false,2,0>, cudaFuncAttributeMaxDynamicSharedMemorySize, GSM_TOTAL);
    cudaFuncSetAttribute(attn_k,           cudaFuncAttributeMaxDynamicSharedMemorySize, ATT_SMEM);

    // launch order: #3 (0-based) is the objtok GEMM -> that's what ncu profiles
    tsplit_k<<<dim3(DD/32, DD/32, 1), 256>>>(bw2, whi + OFF_BW2, DD, DD, 0, 0);         // 0
    box_k<<<NOBJ, 128>>>(boxes, bw1, bb1, blg, blb, bxa);                               // 1
    gather_k<<<NOBJ, 128>>>(objs, obj_emb, objbase);                                    // 2
    gemm2<false,1,0><<<dim3(DD/BN, NOBJ/BM), 256, GSM_TOTAL>>>(                         // 3
        bxa, whi + OFF_BW2, bb2, objbase, objtok, DD, DD);
    first_k<<<(NB + 127)/128, 128>>>(t2i, first);                                       // 4

    // z-batched weight prep (one kernel per weight class)
    tsplit_k<<<dim3(DD/32, DD/32, DEPTH), 256>>>(wq,  whi + OFF_QKV(0),          DD, DD, (size_t)DD*DD, (size_t)LYR_STRIDE);
    tsplit_k<<<dim3(DD/32, DD/32, DEPTH), 256>>>(wk,  whi + OFF_QKV(0) + 262144, DD, DD, (size_t)DD*DD, (size_t)LYR_STRIDE);
    tsplit_k<<<dim3(DD/32, DD/32, DEPTH), 256>>>(wv,  whi + OFF_QKV(0) + 524288, DD, DD, (size_t)DD*DD, (size_t)LYR_STRIDE);
    tsplit_k<<<dim3(DD/32, DD/32, DEPTH), 256>>>(wo,  whi + OFF_WO(0),           DD, DD, (size_t)DD*DD, (size_t)LYR_STRIDE);
    tsplit_k<<<dim3(FF/32, DD/32, DEPTH), 256>>>(wf1, whi + OFF_F1(0),           DD, FF, (size_t)DD*FF, (size_t)LYR_STRIDE);
    tsplit_k<<<dim3(DD/32, FF/32, DEPTH), 256>>>(wf2, whi + OFF_F2(0),           FF, DD, (size_t)FF*DD, (size_t)LYR_STRIDE);
    packb_k<<<(DEPTH*QS + 255)/256, 256>>>(bq, bk, bv, bqkv);
    cudaMemsetAsync(x, 0, (size_t)BMT * DD * sizeof(__half));
    cudaMemsetAsync(mask, 0, BMT);
    scatter_k<<<dim3(NTRI, 3), 128>>>(triples, t2i, first, objtok, pred_emb, x, mask);

    // ---- transformer layers ----
    const dim3 gQKV(QS/BN, BMT/BM);   // (12, 512)
    const dim3 gD  (DD/BN, BMT/BM);   // (4, 512)
    const dim3 gF1 (FF/BN, BMT/BM);   // (16, 512)
    for (int l = 0; l < DEPTH; l++) {
        ln_k<<<BMT, 128>>>(x, ln1g + l*DD, ln1b + l*DD, ha);
        gemm2<false,0,1><<<gQKV, 256, GSM_TOTAL>>>(
            ha, whi + OFF_QKV(l), bqkv + l*QS, nullptr, qkv, DD, QS);
        attn_k<<<dim3(NB, NH/2), 256, ATT_SMEM>>>(qkv, mask, ata);
        gemm2<false,2,1><<<gD, 256, GSM_TOTAL>>>(
            ata, whi + OFF_WO(l), bo + l*DD, x, x, DD, DD);
        ln_k<<<BMT, 128>>>(x, ln2g + l*DD, ln2b + l*DD, ha);
        gemm2<true,0,1><<<gF1, 256, GSM_TOTAL>>>(
            ha, whi + OFF_F1(l), bf1 + l*FF, nullptr, ffa, DD, FF);
        if (l == DEPTH - 1) {
            gemm2<false,2,0><<<gD, 256, GSM_TOTAL>>>(
                ffa, whi + OFF_F2(l), bf2 + l*DD, x, outp, FF, DD);
        } else {
            gemm2<false,2,1><<<gD, 256, GSM_TOTAL>>>(
                ffa, whi + OFF_F2(l), bf2 + l*DD, x, x, FF, DD);
        }
    }
}